// round 8
// baseline (speedup 1.0000x reference)
#include <cuda_runtime.h>
#include <cuda_bf16.h>
#include <cstdint>

#define D 128
#define NTHREADS 256
#define BM 64           // block M tile (rows)
#define PA 68           // A-tile pair-word row pitch (64 kp + 4 pad); bank = 4r+t, conflict-free
#define PB 136          // B-tile row pitch over n=128 (+8 pad); bank = 8t+r, conflict-free

#define MAX_N 50000
#define MAX_E 800000

// Scratch (static device globals; no allocations allowed)
__device__ float g_P1[(size_t)MAX_N * D];   // X @ msg_w1[0:128]
__device__ float g_P2[(size_t)MAX_N * D];   // X @ msg_w1[128:256] + msg_b1
__device__ float g_H [(size_t)MAX_N * D];   // per-dst sum of relu(P1[src]+P2'[dst])
__device__ float g_deg[MAX_N];              // in-degree (float)
__device__ float g_Wp[D * D];               // msg_w2 @ upd_w1[128:256]
__device__ float g_bp[D];                   // msg_b2 @ upd_w1[128:256]

// Pre-split weight planes: [sel][plane(hi=0,lo=1)][kp 0..63][n 0..127] packed bf16x2
// sel: 0=mw1_top 1=mw1_bot 2=uw1_top 3=Wp 4=uw2
__device__ uint32_t g_WS[5 * 2 * 64 * 128];

// CSR scratch
__device__ int g_cnt[MAX_N];
__device__ int g_off[MAX_N + 1];
__device__ int g_cur[MAX_N];
__device__ int g_esrc[MAX_E];

// ---------------------------------------------------------------------------
__global__ void zero_cnt_kernel(int N) {
    int i = blockIdx.x * blockDim.x + threadIdx.x;
    if (i < N) g_cnt[i] = 0;
}

// ---------------------------------------------------------------------------
// W' = msg_w2 @ upd_w1_bot  and  b' = msg_b2 @ upd_w1_bot   (tiny, per launch)
__global__ void wprime_kernel(const float* __restrict__ w2,
                              const float* __restrict__ uw1,
                              const float* __restrict__ b2) {
    int idx = blockIdx.x * 256 + threadIdx.x;
    if (blockIdx.x < 64) {
        int k = idx >> 7;
        int c = idx & 127;
        float s = 0.f;
        #pragma unroll 8
        for (int j = 0; j < D; ++j)
            s += __ldg(w2 + k * D + j) * __ldg(uw1 + (size_t)(D + j) * D + c);
        g_Wp[k * D + c] = s;
    } else if (threadIdx.x < D) {
        int c = threadIdx.x;
        float s = 0.f;
        #pragma unroll 8
        for (int j = 0; j < D; ++j)
            s += __ldg(b2 + j) * __ldg(uw1 + (size_t)(D + j) * D + c);
        g_bp[c] = s;
    }
}

// ---------------------------------------------------------------------------
// Split (x,y) [k, k+1 adjacent] into hi/lo packed bf16x2 words.
__device__ __forceinline__ void split2(float x, float y, uint32_t& hi, uint32_t& lo) {
    __nv_bfloat162 hp = __floats2bfloat162_rn(x, y);
    float xh = __low2float(hp);
    float yh = __high2float(hp);
    __nv_bfloat162 lp = __floats2bfloat162_rn(x - xh, y - yh);
    hi = *reinterpret_cast<uint32_t*>(&hp);
    lo = *reinterpret_cast<uint32_t*>(&lp);
}

// Split all five B matrices into g_WS (run after wprime; sel=3 reads g_Wp).
__global__ void split_weights_kernel(const float* __restrict__ mw1,
                                     const float* __restrict__ uw1,
                                     const float* __restrict__ uw2) {
    int sel = blockIdx.y;
    const float* w;
    if      (sel == 0) w = mw1;
    else if (sel == 1) w = mw1 + (size_t)128 * D;
    else if (sel == 2) w = uw1;
    else if (sel == 3) w = g_Wp;
    else               w = uw2;
    int i = blockIdx.x * 256 + threadIdx.x;   // 0..8191
    if (i < 8192) {
        int kp = i >> 7, n = i & 127;
        float xv = __ldg(w + (size_t)(2 * kp) * D + n);
        float yv = __ldg(w + (size_t)(2 * kp + 1) * D + n);
        uint32_t h, l;
        split2(xv, yv, h, l);
        g_WS[(size_t)sel * 16384 + kp * 128 + n]        = h;
        g_WS[(size_t)sel * 16384 + 8192 + kp * 128 + n] = l;
    }
}

// ---------------------------------------------------------------------------
// CSR build: histogram -> scan -> scatter
__global__ void hist_kernel(const int* __restrict__ ei, int E) {
    int i = blockIdx.x * blockDim.x + threadIdx.x;
    if (i < E) {
        int2 e = __ldg((const int2*)ei + i);
        atomicAdd(&g_cnt[e.y], 1);
    }
}

__global__ __launch_bounds__(1024) void scan_kernel(int N, int E) {
    __shared__ int part[1024];
    int t = threadIdx.x;
    int chunk = (N + 1023) >> 10;
    int beg = t * chunk;
    int end = beg + chunk; if (end > N) end = N;
    int s = 0;
    for (int i = beg; i < end; ++i) s += g_cnt[i];
    part[t] = s;
    __syncthreads();
    for (int off = 1; off < 1024; off <<= 1) {
        int v = (t >= off) ? part[t - off] : 0;
        __syncthreads();
        part[t] += v;
        __syncthreads();
    }
    int run = (t == 0) ? 0 : part[t - 1];
    for (int i = beg; i < end; ++i) {
        g_off[i] = run;
        g_cur[i] = run;
        run += g_cnt[i];
    }
    if (t == 0) g_off[N] = E;
}

__global__ void scatter_kernel(const int* __restrict__ ei, int E) {
    int i = blockIdx.x * blockDim.x + threadIdx.x;
    if (i < E) {
        int2 e = __ldg((const int2*)ei + i);
        int pos = atomicAdd(&g_cur[e.y], 1);
        g_esrc[pos] = e.x;
    }
}

// ---------------------------------------------------------------------------
// Gather: one warp per dst node. H[d] = sum_e relu(P1[src_e] + P2'[d]); no atomics.
__global__ __launch_bounds__(256)
void gather_kernel(int N) {
    int d = (int)((blockIdx.x * 256 + threadIdx.x) >> 5);
    int lane = threadIdx.x & 31;
    if (d >= N) return;
    int beg = __ldg(&g_off[d]);
    int end = __ldg(&g_off[d + 1]);
    float4 p2 = __ldg((const float4*)(g_P2 + (size_t)d * D) + lane);
    float4 acc = make_float4(0.f, 0.f, 0.f, 0.f);
    int j = beg;
    for (; j + 1 < end; j += 2) {
        int s0 = __ldg(g_esrc + j);
        int s1 = __ldg(g_esrc + j + 1);
        float4 a = __ldg((const float4*)(g_P1 + (size_t)s0 * D) + lane);
        float4 b = __ldg((const float4*)(g_P1 + (size_t)s1 * D) + lane);
        acc.x += fmaxf(a.x + p2.x, 0.f) + fmaxf(b.x + p2.x, 0.f);
        acc.y += fmaxf(a.y + p2.y, 0.f) + fmaxf(b.y + p2.y, 0.f);
        acc.z += fmaxf(a.z + p2.z, 0.f) + fmaxf(b.z + p2.z, 0.f);
        acc.w += fmaxf(a.w + p2.w, 0.f) + fmaxf(b.w + p2.w, 0.f);
    }
    if (j < end) {
        int s0 = __ldg(g_esrc + j);
        float4 a = __ldg((const float4*)(g_P1 + (size_t)s0 * D) + lane);
        acc.x += fmaxf(a.x + p2.x, 0.f);
        acc.y += fmaxf(a.y + p2.y, 0.f);
        acc.z += fmaxf(a.z + p2.z, 0.f);
        acc.w += fmaxf(a.w + p2.w, 0.f);
    }
    *((float4*)(g_H + (size_t)d * D) + lane) = acc;
    if (lane == 0) g_deg[d] = (float)(end - beg);
}

// ===========================================================================
// bf16x3 tensor-core GEMM: acc += Ah*Bh + Al*Bh + Ah*Bl (Al*Bl dropped, ~2^-16)
// Block tile 64x128 (102KB smem -> 2 blocks/SM), warp grid 2x4 -> m32 x n32.
// ===========================================================================

__device__ __forceinline__ void mma16816(float c[4],
                                         uint32_t a0, uint32_t a1, uint32_t a2, uint32_t a3,
                                         uint32_t b0, uint32_t b1) {
    asm volatile(
        "mma.sync.aligned.m16n8k16.row.col.f32.bf16.bf16.f32 "
        "{%0,%1,%2,%3}, {%4,%5,%6,%7}, {%8,%9}, {%0,%1,%2,%3};"
        : "+f"(c[0]), "+f"(c[1]), "+f"(c[2]), "+f"(c[3])
        : "r"(a0), "r"(a1), "r"(a2), "r"(a3), "r"(b0), "r"(b1));
}

// Fill A tile (BM rows x 64 kp), pre-split, from global f32 [rows][128].
__device__ __forceinline__ void fill_A(uint32_t* sA0, uint32_t* sA1,
                                       const float* __restrict__ src,
                                       int rowBase, int N, int tid) {
    for (int i = tid; i < BM * 64; i += NTHREADS) {
        int m = i >> 6, kp = i & 63;
        int gm = rowBase + m;
        float2 v = make_float2(0.f, 0.f);
        if (gm < N) v = *(const float2*)(src + (size_t)gm * D + 2 * kp);
        uint32_t h, l;
        split2(v.x, v.y, h, l);
        sA0[m * PA + kp] = h;
        sA1[m * PA + kp] = l;
    }
}

// Copy pre-split B matrix sel (full 64 kp x 128 n, both planes) into smem.
__device__ __forceinline__ void fill_B(uint32_t* sB0, uint32_t* sB1, int sel, int tid) {
    const uint32_t* src = g_WS + (size_t)sel * 16384;
    for (int i = tid; i < 64 * 32; i += NTHREADS) {
        int kp = i >> 5, n4 = (i & 31) * 4;
        uint4 h = *(const uint4*)(src + kp * 128 + n4);
        uint4 l = *(const uint4*)(src + 8192 + kp * 128 + n4);
        *(uint4*)(sB0 + kp * PB + n4) = h;
        *(uint4*)(sB1 + kp * PB + n4) = l;
    }
}

// Full-K mma pass. Warp tile: rows [32*wm, +32), cols [32*wn, +32).
__device__ __forceinline__ void mma_full(const uint32_t* sA0, const uint32_t* sA1,
                                         const uint32_t* sB0, const uint32_t* sB1,
                                         float acc[2][4][4], int wm, int wn, int r, int t) {
    #pragma unroll
    for (int ks = 0; ks < 8; ++ks) {
        int kpA = ks * 8;
        uint32_t ah[2][4], al[2][4];
        #pragma unroll
        for (int mi = 0; mi < 2; ++mi) {
            int m0 = 32 * wm + 16 * mi + r;
            const uint32_t* p0 = sA0 + m0 * PA + kpA;
            const uint32_t* p1 = sA0 + (m0 + 8) * PA + kpA;
            const uint32_t* q0 = sA1 + m0 * PA + kpA;
            const uint32_t* q1 = sA1 + (m0 + 8) * PA + kpA;
            ah[mi][0] = p0[t]; ah[mi][1] = p1[t]; ah[mi][2] = p0[4 + t]; ah[mi][3] = p1[4 + t];
            al[mi][0] = q0[t]; al[mi][1] = q1[t]; al[mi][2] = q0[4 + t]; al[mi][3] = q1[4 + t];
        }
        #pragma unroll
        for (int ni = 0; ni < 4; ++ni) {
            int n = 32 * wn + 8 * ni + r;
            uint32_t bh0 = sB0[(ks * 8 + t) * PB + n];
            uint32_t bh1 = sB0[(ks * 8 + 4 + t) * PB + n];
            uint32_t bl0 = sB1[(ks * 8 + t) * PB + n];
            uint32_t bl1 = sB1[(ks * 8 + 4 + t) * PB + n];
            #pragma unroll
            for (int mi = 0; mi < 2; ++mi) {
                mma16816(acc[mi][ni], ah[mi][0], ah[mi][1], ah[mi][2], ah[mi][3], bh0, bh1);
                mma16816(acc[mi][ni], al[mi][0], al[mi][1], al[mi][2], al[mi][3], bh0, bh1);
                mma16816(acc[mi][ni], ah[mi][0], ah[mi][1], ah[mi][2], ah[mi][3], bl0, bl1);
            }
        }
    }
}

__device__ __forceinline__ void zero_acc(float acc[2][4][4]) {
    #pragma unroll
    for (int mi = 0; mi < 2; ++mi)
        #pragma unroll
        for (int ni = 0; ni < 4; ++ni)
            #pragma unroll
            for (int q = 0; q < 4; ++q) acc[mi][ni][q] = 0.f;
}

// smem word offsets
#define SA0_OFF 0
#define SA1_OFF (BM * PA)
#define SB0_OFF (2 * BM * PA)
#define SB1_OFF (2 * BM * PA + 64 * PB)
#define SMEM_MMA_BYTES ((2 * BM * PA + 2 * 64 * PB) * 4)   // 104448 B -> 2 blocks/SM

// ---------------------------------------------------------------------------
// K1: P1 = X @ mw1_top, P2 = X @ mw1_bot + b1
__global__ __launch_bounds__(256, 2)
void precompute_mma(const float* __restrict__ x, const float* __restrict__ b1, int N) {
    extern __shared__ uint32_t smu[];
    uint32_t* sA0 = smu + SA0_OFF;
    uint32_t* sA1 = smu + SA1_OFF;
    uint32_t* sB0 = smu + SB0_OFF;
    uint32_t* sB1 = smu + SB1_OFF;
    const int tid = threadIdx.x;
    const int wid = tid >> 5, lane = tid & 31;
    const int wm = wid >> 2, wn = wid & 3, r = lane >> 2, t = lane & 3;
    const int rowBase = blockIdx.x * BM;

    fill_A(sA0, sA1, x, rowBase, N, tid);
    fill_B(sB0, sB1, 0, tid);
    __syncthreads();

    float acc[2][4][4];
    zero_acc(acc);
    mma_full(sA0, sA1, sB0, sB1, acc, wm, wn, r, t);
    __syncthreads();                       // release B before refill

    #pragma unroll
    for (int mi = 0; mi < 2; ++mi) {
        int m0 = rowBase + 32 * wm + 16 * mi + r;
        int m1 = m0 + 8;
        #pragma unroll
        for (int ni = 0; ni < 4; ++ni) {
            int col = 32 * wn + 8 * ni + 2 * t;
            if (m0 < N) *(float2*)(g_P1 + (size_t)m0 * D + col) = make_float2(acc[mi][ni][0], acc[mi][ni][1]);
            if (m1 < N) *(float2*)(g_P1 + (size_t)m1 * D + col) = make_float2(acc[mi][ni][2], acc[mi][ni][3]);
        }
    }

    fill_B(sB0, sB1, 1, tid);
    __syncthreads();
    zero_acc(acc);
    mma_full(sA0, sA1, sB0, sB1, acc, wm, wn, r, t);

    #pragma unroll
    for (int mi = 0; mi < 2; ++mi) {
        int m0 = rowBase + 32 * wm + 16 * mi + r;
        int m1 = m0 + 8;
        #pragma unroll
        for (int ni = 0; ni < 4; ++ni) {
            int col = 32 * wn + 8 * ni + 2 * t;
            float b0 = __ldg(b1 + col), bx = __ldg(b1 + col + 1);
            if (m0 < N) *(float2*)(g_P2 + (size_t)m0 * D + col) = make_float2(acc[mi][ni][0] + b0, acc[mi][ni][1] + bx);
            if (m1 < N) *(float2*)(g_P2 + (size_t)m1 * D + col) = make_float2(acc[mi][ni][2] + b0, acc[mi][ni][3] + bx);
        }
    }
}

// ---------------------------------------------------------------------------
// K3: out = relu(X@uw1_top + H@W' + deg*b' + ub1) @ uw2 + ub2
__global__ __launch_bounds__(256, 2)
void node_mma(const float* __restrict__ x, const float* __restrict__ ub1,
              const float* __restrict__ ub2, float* __restrict__ out, int N) {
    extern __shared__ uint32_t smu[];
    uint32_t* sA0 = smu + SA0_OFF;
    uint32_t* sA1 = smu + SA1_OFF;
    uint32_t* sB0 = smu + SB0_OFF;
    uint32_t* sB1 = smu + SB1_OFF;
    const int tid = threadIdx.x;
    const int wid = tid >> 5, lane = tid & 31;
    const int wm = wid >> 2, wn = wid & 3, r = lane >> 2, t = lane & 3;
    const int rowBase = blockIdx.x * BM;

    float acc[2][4][4];
    zero_acc(acc);

    // ---- stage 1a: X @ uw1_top ----
    fill_A(sA0, sA1, x, rowBase, N, tid);
    fill_B(sB0, sB1, 2, tid);
    __syncthreads();
    mma_full(sA0, sA1, sB0, sB1, acc, wm, wn, r, t);
    __syncthreads();

    // ---- stage 1b: + H @ Wp ----
    fill_A(sA0, sA1, g_H, rowBase, N, tid);
    fill_B(sB0, sB1, 3, tid);
    __syncthreads();
    mma_full(sA0, sA1, sB0, sB1, acc, wm, wn, r, t);
    __syncthreads();                       // all reads of sA done before epilogue writes

    // ---- epilogue 1: + deg*b' + ub1, relu ; re-split hidden into sA planes ----
    #pragma unroll
    for (int mi = 0; mi < 2; ++mi) {
        int m0 = rowBase + 32 * wm + 16 * mi + r;
        int m1 = m0 + 8;
        float dg0 = (m0 < N) ? __ldg(g_deg + m0) : 0.f;
        float dg1 = (m1 < N) ? __ldg(g_deg + m1) : 0.f;
        #pragma unroll
        for (int ni = 0; ni < 4; ++ni) {
            int col = 32 * wn + 8 * ni + 2 * t;
            float bp0 = g_bp[col], bp1 = g_bp[col + 1];
            float u0 = __ldg(ub1 + col), u1 = __ldg(ub1 + col + 1);
            float v00 = fmaxf(acc[mi][ni][0] + dg0 * bp0 + u0, 0.f);
            float v01 = fmaxf(acc[mi][ni][1] + dg0 * bp1 + u1, 0.f);
            float v10 = fmaxf(acc[mi][ni][2] + dg1 * bp0 + u0, 0.f);
            float v11 = fmaxf(acc[mi][ni][3] + dg1 * bp1 + u1, 0.f);
            int kp = 16 * wn + 4 * ni + t;
            int lm0 = 32 * wm + 16 * mi + r;
            uint32_t h, l;
            split2(v00, v01, h, l);
            sA0[lm0 * PA + kp] = h;
            sA1[lm0 * PA + kp] = l;
            split2(v10, v11, h, l);
            sA0[(lm0 + 8) * PA + kp] = h;
            sA1[(lm0 + 8) * PA + kp] = l;
        }
    }
    fill_B(sB0, sB1, 4, tid);              // overlaps epilogue; disjoint smem region
    __syncthreads();

    // ---- stage 2: hidden @ uw2 ----
    zero_acc(acc);
    mma_full(sA0, sA1, sB0, sB1, acc, wm, wn, r, t);

    #pragma unroll
    for (int mi = 0; mi < 2; ++mi) {
        int m0 = rowBase + 32 * wm + 16 * mi + r;
        int m1 = m0 + 8;
        #pragma unroll
        for (int ni = 0; ni < 4; ++ni) {
            int col = 32 * wn + 8 * ni + 2 * t;
            float b0 = __ldg(ub2 + col), bx = __ldg(ub2 + col + 1);
            if (m0 < N) *(float2*)(out + (size_t)m0 * D + col) = make_float2(acc[mi][ni][0] + b0, acc[mi][ni][1] + bx);
            if (m1 < N) *(float2*)(out + (size_t)m1 * D + col) = make_float2(acc[mi][ni][2] + b0, acc[mi][ni][3] + bx);
        }
    }
}

// ---------------------------------------------------------------------------
extern "C" void kernel_launch(void* const* d_in, const int* in_sizes, int n_in,
                              void* d_out, int out_size) {
    const float* x   = (const float*)d_in[0];
    const int*   ei  = (const int*)d_in[1];     // int64 downcast to int32 by harness
    const float* mw1 = (const float*)d_in[2];
    const float* mb1 = (const float*)d_in[3];
    const float* mw2 = (const float*)d_in[4];
    const float* mb2 = (const float*)d_in[5];
    const float* uw1 = (const float*)d_in[6];
    const float* ub1 = (const float*)d_in[7];
    const float* uw2 = (const float*)d_in[8];
    const float* ub2 = (const float*)d_in[9];
    float* out = (float*)d_out;

    int N = in_sizes[0] / D;
    int E = in_sizes[1] / 2;

    cudaFuncSetAttribute(precompute_mma, cudaFuncAttributeMaxDynamicSharedMemorySize, SMEM_MMA_BYTES);
    cudaFuncSetAttribute(node_mma,       cudaFuncAttributeMaxDynamicSharedMemorySize, SMEM_MMA_BYTES);

    zero_cnt_kernel<<<(N + 255) / 256, 256>>>(N);
    wprime_kernel<<<65, 256>>>(mw2, uw1, mb2);
    split_weights_kernel<<<dim3(32, 5), 256>>>(mw1, uw1, uw2);

    int nblk = (N + BM - 1) / BM;
    precompute_mma<<<nblk, NTHREADS, SMEM_MMA_BYTES>>>(x, mb1, N);

    int eblk = (E + 255) / 256;
    hist_kernel<<<eblk, 256>>>(ei, E);
    scan_kernel<<<1, 1024>>>(N, E);
    scatter_kernel<<<eblk, 256>>>(ei, E);
    gather_kernel<<<(N * 32 + 255) / 256, 256>>>(N);

    node_mma<<<nblk, NTHREADS, SMEM_MMA_BYTES>>>(x, ub1, ub2, out, N);
}

// round 10
// speedup vs baseline: 1.2793x; 1.2793x over previous
#include <cuda_runtime.h>
#include <cuda_bf16.h>
#include <cstdint>

#define D 128
#define NTHREADS 256
#define PA 68           // A-tile pair-word row pitch (64 kp + 4 pad); bank = 4r+t, conflict-free
#define PB 136          // B-tile row pitch over n=128 (+8 pad); bank = 8t+r, conflict-free

#define MAX_N 50000
#define MAX_E 800000

// Scratch (static device globals; no allocations allowed)
__device__ float g_P1[(size_t)MAX_N * D];   // X @ msg_w1[0:128]
__device__ float g_P2[(size_t)MAX_N * D];   // X @ msg_w1[128:256] + msg_b1
__device__ float g_H [(size_t)MAX_N * D];   // per-dst sum of relu(P1[src]+P2'[dst])
__device__ float g_deg[MAX_N];              // in-degree (float)
__device__ float g_Wp[D * D];               // msg_w2 @ upd_w1[128:256]
__device__ float g_bp[D];                   // msg_b2 @ upd_w1[128:256]

// Pre-split weight planes: [sel][plane(hi=0,lo=1)][kp 0..63][n 0..127] packed bf16x2
// sel: 0=mw1_top 1=mw1_bot 2=uw1_top 3=Wp 4=uw2
__device__ uint32_t g_WS[5 * 2 * 64 * 128];

// CSR scratch
__device__ int g_cnt[MAX_N];
__device__ int g_off[MAX_N + 1];
__device__ int g_cur[MAX_N];
__device__ int g_esrc[MAX_E];

// ---------------------------------------------------------------------------
__global__ void zero_cnt_kernel(int N) {
    int i = blockIdx.x * blockDim.x + threadIdx.x;
    if (i < N) g_cnt[i] = 0;
}

// ---------------------------------------------------------------------------
// W' = msg_w2 @ upd_w1_bot  and  b' = msg_b2 @ upd_w1_bot   (tiny, per launch)
__global__ void wprime_kernel(const float* __restrict__ w2,
                              const float* __restrict__ uw1,
                              const float* __restrict__ b2) {
    int idx = blockIdx.x * 256 + threadIdx.x;
    if (blockIdx.x < 64) {
        int k = idx >> 7;
        int c = idx & 127;
        float s = 0.f;
        #pragma unroll 8
        for (int j = 0; j < D; ++j)
            s += __ldg(w2 + k * D + j) * __ldg(uw1 + (size_t)(D + j) * D + c);
        g_Wp[k * D + c] = s;
    } else if (threadIdx.x < D) {
        int c = threadIdx.x;
        float s = 0.f;
        #pragma unroll 8
        for (int j = 0; j < D; ++j)
            s += __ldg(b2 + j) * __ldg(uw1 + (size_t)(D + j) * D + c);
        g_bp[c] = s;
    }
}

// ---------------------------------------------------------------------------
// Split (x,y) [k, k+1 adjacent] into hi/lo packed bf16x2 words.
__device__ __forceinline__ void split2(float x, float y, uint32_t& hi, uint32_t& lo) {
    __nv_bfloat162 hp = __floats2bfloat162_rn(x, y);
    float xh = __low2float(hp);
    float yh = __high2float(hp);
    __nv_bfloat162 lp = __floats2bfloat162_rn(x - xh, y - yh);
    hi = *reinterpret_cast<uint32_t*>(&hp);
    lo = *reinterpret_cast<uint32_t*>(&lp);
}

// Split all five B matrices into g_WS (run after wprime; sel=3 reads g_Wp).
__global__ void split_weights_kernel(const float* __restrict__ mw1,
                                     const float* __restrict__ uw1,
                                     const float* __restrict__ uw2) {
    int sel = blockIdx.y;
    const float* w;
    if      (sel == 0) w = mw1;
    else if (sel == 1) w = mw1 + (size_t)128 * D;
    else if (sel == 2) w = uw1;
    else if (sel == 3) w = g_Wp;
    else               w = uw2;
    int i = blockIdx.x * 256 + threadIdx.x;   // 0..8191
    if (i < 8192) {
        int kp = i >> 7, n = i & 127;
        float xv = __ldg(w + (size_t)(2 * kp) * D + n);
        float yv = __ldg(w + (size_t)(2 * kp + 1) * D + n);
        uint32_t h, l;
        split2(xv, yv, h, l);
        g_WS[(size_t)sel * 16384 + kp * 128 + n]        = h;
        g_WS[(size_t)sel * 16384 + 8192 + kp * 128 + n] = l;
    }
}

// ---------------------------------------------------------------------------
// CSR build: histogram -> scan -> scatter
__global__ void hist_kernel(const int* __restrict__ ei, int E) {
    int i = blockIdx.x * blockDim.x + threadIdx.x;
    if (i < E) {
        int2 e = __ldg((const int2*)ei + i);
        atomicAdd(&g_cnt[e.y], 1);
    }
}

__global__ __launch_bounds__(1024) void scan_kernel(int N, int E) {
    __shared__ int part[1024];
    int t = threadIdx.x;
    int chunk = (N + 1023) >> 10;
    int beg = t * chunk;
    int end = beg + chunk; if (end > N) end = N;
    int s = 0;
    for (int i = beg; i < end; ++i) s += g_cnt[i];
    part[t] = s;
    __syncthreads();
    for (int off = 1; off < 1024; off <<= 1) {
        int v = (t >= off) ? part[t - off] : 0;
        __syncthreads();
        part[t] += v;
        __syncthreads();
    }
    int run = (t == 0) ? 0 : part[t - 1];
    for (int i = beg; i < end; ++i) {
        g_off[i] = run;
        g_cur[i] = run;
        run += g_cnt[i];
    }
    if (t == 0) g_off[N] = E;
}

__global__ void scatter_kernel(const int* __restrict__ ei, int E) {
    int i = blockIdx.x * blockDim.x + threadIdx.x;
    if (i < E) {
        int2 e = __ldg((const int2*)ei + i);
        int pos = atomicAdd(&g_cur[e.y], 1);
        g_esrc[pos] = e.x;
    }
}

// ---------------------------------------------------------------------------
// Gather: one warp per dst node. H[d] = sum_e relu(P1[src_e] + P2'[d]); no atomics.
__global__ __launch_bounds__(256)
void gather_kernel(int N) {
    int d = (int)((blockIdx.x * 256 + threadIdx.x) >> 5);
    int lane = threadIdx.x & 31;
    if (d >= N) return;
    int beg = __ldg(&g_off[d]);
    int end = __ldg(&g_off[d + 1]);
    float4 p2 = __ldg((const float4*)(g_P2 + (size_t)d * D) + lane);
    float4 acc = make_float4(0.f, 0.f, 0.f, 0.f);
    int j = beg;
    for (; j + 1 < end; j += 2) {
        int s0 = __ldg(g_esrc + j);
        int s1 = __ldg(g_esrc + j + 1);
        float4 a = __ldg((const float4*)(g_P1 + (size_t)s0 * D) + lane);
        float4 b = __ldg((const float4*)(g_P1 + (size_t)s1 * D) + lane);
        acc.x += fmaxf(a.x + p2.x, 0.f) + fmaxf(b.x + p2.x, 0.f);
        acc.y += fmaxf(a.y + p2.y, 0.f) + fmaxf(b.y + p2.y, 0.f);
        acc.z += fmaxf(a.z + p2.z, 0.f) + fmaxf(b.z + p2.z, 0.f);
        acc.w += fmaxf(a.w + p2.w, 0.f) + fmaxf(b.w + p2.w, 0.f);
    }
    if (j < end) {
        int s0 = __ldg(g_esrc + j);
        float4 a = __ldg((const float4*)(g_P1 + (size_t)s0 * D) + lane);
        acc.x += fmaxf(a.x + p2.x, 0.f);
        acc.y += fmaxf(a.y + p2.y, 0.f);
        acc.z += fmaxf(a.z + p2.z, 0.f);
        acc.w += fmaxf(a.w + p2.w, 0.f);
    }
    *((float4*)(g_H + (size_t)d * D) + lane) = acc;
    if (lane == 0) g_deg[d] = (float)(end - beg);
}

// ===========================================================================
// bf16x3 tensor-core GEMM: acc += Ah*Bh + Al*Bh + Ah*Bl (Al*Bl dropped, ~2^-16)
// Block tile 128x128, warp grid 2x4 -> warp tile m64 x n32, full-K resident.
// (round-7 config: measured best at 294.9us; HMMA path saturated at its cap)
// ===========================================================================

__device__ __forceinline__ void mma16816(float c[4],
                                         uint32_t a0, uint32_t a1, uint32_t a2, uint32_t a3,
                                         uint32_t b0, uint32_t b1) {
    asm volatile(
        "mma.sync.aligned.m16n8k16.row.col.f32.bf16.bf16.f32 "
        "{%0,%1,%2,%3}, {%4,%5,%6,%7}, {%8,%9}, {%0,%1,%2,%3};"
        : "+f"(c[0]), "+f"(c[1]), "+f"(c[2]), "+f"(c[3])
        : "r"(a0), "r"(a1), "r"(a2), "r"(a3), "r"(b0), "r"(b1));
}

// Fill A tile (128 rows x 64 kp), pre-split, from global f32 [rows][128].
__device__ __forceinline__ void fill_A(uint32_t* sA0, uint32_t* sA1,
                                       const float* __restrict__ src,
                                       int rowBase, int N, int tid) {
    for (int i = tid; i < 128 * 64; i += NTHREADS) {
        int m = i >> 6, kp = i & 63;
        int gm = rowBase + m;
        float2 v = make_float2(0.f, 0.f);
        if (gm < N) v = *(const float2*)(src + (size_t)gm * D + 2 * kp);
        uint32_t h, l;
        split2(v.x, v.y, h, l);
        sA0[m * PA + kp] = h;
        sA1[m * PA + kp] = l;
    }
}

// Copy pre-split B matrix sel (full 64 kp x 128 n, both planes) into smem.
__device__ __forceinline__ void fill_B(uint32_t* sB0, uint32_t* sB1, int sel, int tid) {
    const uint32_t* src = g_WS + (size_t)sel * 16384;
    for (int i = tid; i < 64 * 32; i += NTHREADS) {
        int kp = i >> 5, n4 = (i & 31) * 4;
        uint4 h = *(const uint4*)(src + kp * 128 + n4);
        uint4 l = *(const uint4*)(src + 8192 + kp * 128 + n4);
        *(uint4*)(sB0 + kp * PB + n4) = h;
        *(uint4*)(sB1 + kp * PB + n4) = l;
    }
}

// Full-K mma pass. Warp tile: rows [64*wm, +64), cols [32*wn, +32).
__device__ __forceinline__ void mma_full(const uint32_t* sA0, const uint32_t* sA1,
                                         const uint32_t* sB0, const uint32_t* sB1,
                                         float acc[4][4][4], int wm, int wn, int r, int t) {
    #pragma unroll
    for (int ks = 0; ks < 8; ++ks) {
        int kpA = ks * 8;
        uint32_t ah[4][4], al[4][4];
        #pragma unroll
        for (int mi = 0; mi < 4; ++mi) {
            int m0 = 64 * wm + 16 * mi + r;
            const uint32_t* p0 = sA0 + m0 * PA + kpA;
            const uint32_t* p1 = sA0 + (m0 + 8) * PA + kpA;
            const uint32_t* q0 = sA1 + m0 * PA + kpA;
            const uint32_t* q1 = sA1 + (m0 + 8) * PA + kpA;
            ah[mi][0] = p0[t]; ah[mi][1] = p1[t]; ah[mi][2] = p0[4 + t]; ah[mi][3] = p1[4 + t];
            al[mi][0] = q0[t]; al[mi][1] = q1[t]; al[mi][2] = q0[4 + t]; al[mi][3] = q1[4 + t];
        }
        #pragma unroll
        for (int ni = 0; ni < 4; ++ni) {
            int n = 32 * wn + 8 * ni + r;
            uint32_t bh0 = sB0[(ks * 8 + t) * PB + n];
            uint32_t bh1 = sB0[(ks * 8 + 4 + t) * PB + n];
            uint32_t bl0 = sB1[(ks * 8 + t) * PB + n];
            uint32_t bl1 = sB1[(ks * 8 + 4 + t) * PB + n];
            #pragma unroll
            for (int mi = 0; mi < 4; ++mi) {
                mma16816(acc[mi][ni], ah[mi][0], ah[mi][1], ah[mi][2], ah[mi][3], bh0, bh1);
                mma16816(acc[mi][ni], al[mi][0], al[mi][1], al[mi][2], al[mi][3], bh0, bh1);
                mma16816(acc[mi][ni], ah[mi][0], ah[mi][1], ah[mi][2], ah[mi][3], bl0, bl1);
            }
        }
    }
}

__device__ __forceinline__ void zero_acc(float acc[4][4][4]) {
    #pragma unroll
    for (int mi = 0; mi < 4; ++mi)
        #pragma unroll
        for (int ni = 0; ni < 4; ++ni)
            #pragma unroll
            for (int q = 0; q < 4; ++q) acc[mi][ni][q] = 0.f;
}

// smem word offsets
#define SA0_OFF 0
#define SA1_OFF (128 * PA)
#define SB0_OFF (2 * 128 * PA)
#define SB1_OFF (2 * 128 * PA + 64 * PB)
#define SMEM_MMA_BYTES ((2 * 128 * PA + 2 * 64 * PB) * 4)   // 139264 B

// ---------------------------------------------------------------------------
// K1: P1 = X @ mw1_top, P2 = X @ mw1_bot + b1
__global__ __launch_bounds__(256)
void precompute_mma(const float* __restrict__ x, const float* __restrict__ b1, int N) {
    extern __shared__ uint32_t smu[];
    uint32_t* sA0 = smu + SA0_OFF;
    uint32_t* sA1 = smu + SA1_OFF;
    uint32_t* sB0 = smu + SB0_OFF;
    uint32_t* sB1 = smu + SB1_OFF;
    const int tid = threadIdx.x;
    const int wid = tid >> 5, lane = tid & 31;
    const int wm = wid >> 2, wn = wid & 3, r = lane >> 2, t = lane & 3;
    const int rowBase = blockIdx.x * 128;

    fill_A(sA0, sA1, x, rowBase, N, tid);
    fill_B(sB0, sB1, 0, tid);
    __syncthreads();

    float acc[4][4][4];
    zero_acc(acc);
    mma_full(sA0, sA1, sB0, sB1, acc, wm, wn, r, t);
    __syncthreads();                       // release B before refill

    #pragma unroll
    for (int mi = 0; mi < 4; ++mi) {
        int m0 = rowBase + 64 * wm + 16 * mi + r;
        int m1 = m0 + 8;
        #pragma unroll
        for (int ni = 0; ni < 4; ++ni) {
            int col = 32 * wn + 8 * ni + 2 * t;
            if (m0 < N) *(float2*)(g_P1 + (size_t)m0 * D + col) = make_float2(acc[mi][ni][0], acc[mi][ni][1]);
            if (m1 < N) *(float2*)(g_P1 + (size_t)m1 * D + col) = make_float2(acc[mi][ni][2], acc[mi][ni][3]);
        }
    }

    fill_B(sB0, sB1, 1, tid);
    __syncthreads();
    zero_acc(acc);
    mma_full(sA0, sA1, sB0, sB1, acc, wm, wn, r, t);

    #pragma unroll
    for (int mi = 0; mi < 4; ++mi) {
        int m0 = rowBase + 64 * wm + 16 * mi + r;
        int m1 = m0 + 8;
        #pragma unroll
        for (int ni = 0; ni < 4; ++ni) {
            int col = 32 * wn + 8 * ni + 2 * t;
            float b0 = __ldg(b1 + col), bx = __ldg(b1 + col + 1);
            if (m0 < N) *(float2*)(g_P2 + (size_t)m0 * D + col) = make_float2(acc[mi][ni][0] + b0, acc[mi][ni][1] + bx);
            if (m1 < N) *(float2*)(g_P2 + (size_t)m1 * D + col) = make_float2(acc[mi][ni][2] + b0, acc[mi][ni][3] + bx);
        }
    }
}

// ---------------------------------------------------------------------------
// K3: out = relu(X@uw1_top + H@W' + deg*b' + ub1) @ uw2 + ub2
__global__ __launch_bounds__(256)
void node_mma(const float* __restrict__ x, const float* __restrict__ ub1,
              const float* __restrict__ ub2, float* __restrict__ out, int N) {
    extern __shared__ uint32_t smu[];
    uint32_t* sA0 = smu + SA0_OFF;
    uint32_t* sA1 = smu + SA1_OFF;
    uint32_t* sB0 = smu + SB0_OFF;
    uint32_t* sB1 = smu + SB1_OFF;
    const int tid = threadIdx.x;
    const int wid = tid >> 5, lane = tid & 31;
    const int wm = wid >> 2, wn = wid & 3, r = lane >> 2, t = lane & 3;
    const int rowBase = blockIdx.x * 128;

    float acc[4][4][4];
    zero_acc(acc);

    // ---- stage 1a: X @ uw1_top ----
    fill_A(sA0, sA1, x, rowBase, N, tid);
    fill_B(sB0, sB1, 2, tid);
    __syncthreads();
    mma_full(sA0, sA1, sB0, sB1, acc, wm, wn, r, t);
    __syncthreads();

    // ---- stage 1b: + H @ Wp ----
    fill_A(sA0, sA1, g_H, rowBase, N, tid);
    fill_B(sB0, sB1, 3, tid);
    __syncthreads();
    mma_full(sA0, sA1, sB0, sB1, acc, wm, wn, r, t);
    __syncthreads();                       // all reads of sA done before epilogue writes

    // ---- epilogue 1: + deg*b' + ub1, relu ; re-split hidden into sA planes ----
    #pragma unroll
    for (int mi = 0; mi < 4; ++mi) {
        int m0 = rowBase + 64 * wm + 16 * mi + r;
        int m1 = m0 + 8;
        float dg0 = (m0 < N) ? __ldg(g_deg + m0) : 0.f;
        float dg1 = (m1 < N) ? __ldg(g_deg + m1) : 0.f;
        #pragma unroll
        for (int ni = 0; ni < 4; ++ni) {
            int col = 32 * wn + 8 * ni + 2 * t;
            float bp0 = g_bp[col], bp1 = g_bp[col + 1];
            float u0 = __ldg(ub1 + col), u1 = __ldg(ub1 + col + 1);
            float v00 = fmaxf(acc[mi][ni][0] + dg0 * bp0 + u0, 0.f);
            float v01 = fmaxf(acc[mi][ni][1] + dg0 * bp1 + u1, 0.f);
            float v10 = fmaxf(acc[mi][ni][2] + dg1 * bp0 + u0, 0.f);
            float v11 = fmaxf(acc[mi][ni][3] + dg1 * bp1 + u1, 0.f);
            int kp = 16 * wn + 4 * ni + t;
            int lm0 = 64 * wm + 16 * mi + r;
            uint32_t h, l;
            split2(v00, v01, h, l);
            sA0[lm0 * PA + kp] = h;
            sA1[lm0 * PA + kp] = l;
            split2(v10, v11, h, l);
            sA0[(lm0 + 8) * PA + kp] = h;
            sA1[(lm0 + 8) * PA + kp] = l;
        }
    }
    fill_B(sB0, sB1, 4, tid);              // overlaps epilogue; disjoint smem region
    __syncthreads();

    // ---- stage 2: hidden @ uw2 ----
    zero_acc(acc);
    mma_full(sA0, sA1, sB0, sB1, acc, wm, wn, r, t);

    #pragma unroll
    for (int mi = 0; mi < 4; ++mi) {
        int m0 = rowBase + 64 * wm + 16 * mi + r;
        int m1 = m0 + 8;
        #pragma unroll
        for (int ni = 0; ni < 4; ++ni) {
            int col = 32 * wn + 8 * ni + 2 * t;
            float b0 = __ldg(ub2 + col), bx = __ldg(ub2 + col + 1);
            if (m0 < N) *(float2*)(out + (size_t)m0 * D + col) = make_float2(acc[mi][ni][0] + b0, acc[mi][ni][1] + bx);
            if (m1 < N) *(float2*)(out + (size_t)m1 * D + col) = make_float2(acc[mi][ni][2] + b0, acc[mi][ni][3] + bx);
        }
    }
}

// ---------------------------------------------------------------------------
extern "C" void kernel_launch(void* const* d_in, const int* in_sizes, int n_in,
                              void* d_out, int out_size) {
    const float* x   = (const float*)d_in[0];
    const int*   ei  = (const int*)d_in[1];     // int64 downcast to int32 by harness
    const float* mw1 = (const float*)d_in[2];
    const float* mb1 = (const float*)d_in[3];
    const float* mw2 = (const float*)d_in[4];
    const float* mb2 = (const float*)d_in[5];
    const float* uw1 = (const float*)d_in[6];
    const float* ub1 = (const float*)d_in[7];
    const float* uw2 = (const float*)d_in[8];
    const float* ub2 = (const float*)d_in[9];
    float* out = (float*)d_out;

    int N = in_sizes[0] / D;
    int E = in_sizes[1] / 2;

    cudaFuncSetAttribute(precompute_mma, cudaFuncAttributeMaxDynamicSharedMemorySize, SMEM_MMA_BYTES);
    cudaFuncSetAttribute(node_mma,       cudaFuncAttributeMaxDynamicSharedMemorySize, SMEM_MMA_BYTES);

    // One-time side-stream + events (created on the uncaptured correctness
    // call; reused as-is during graph capture). No device memory is allocated
    // here; all scratch remains the static __device__ globals above.
    static cudaStream_t s2 = nullptr;
    static cudaEvent_t evFork = nullptr, evJoin = nullptr;
    if (s2 == nullptr) {
        cudaStreamCreateWithFlags(&s2, cudaStreamNonBlocking);
        cudaEventCreateWithFlags(&evFork, cudaEventDisableTiming);
        cudaEventCreateWithFlags(&evJoin, cudaEventDisableTiming);
    }

    int eblk = (E + 255) / 256;
    int nblk = (N + 127) / 128;

    // main stream: counters zeroed first (hist depends on them)
    zero_cnt_kernel<<<(N + 255) / 256, 256>>>(N);

    // fork: CSR build (depends only on ei) runs concurrently with weight prep + K1
    cudaEventRecord(evFork, 0);
    cudaStreamWaitEvent(s2, evFork, 0);
    hist_kernel<<<eblk, 256, 0, s2>>>(ei, E);
    scan_kernel<<<1, 1024, 0, s2>>>(N, E);
    scatter_kernel<<<eblk, 256, 0, s2>>>(ei, E);
    cudaEventRecord(evJoin, s2);

    // main stream: weight prep + precompute GEMMs (tensor-bound, hides CSR)
    wprime_kernel<<<65, 256>>>(mw2, uw1, mb2);
    split_weights_kernel<<<dim3(32, 5), 256>>>(mw1, uw1, uw2);
    precompute_mma<<<nblk, NTHREADS, SMEM_MMA_BYTES>>>(x, mb1, N);

    // join: gather needs both P1/P2 (main) and off/esrc (s2)
    cudaStreamWaitEvent(0, evJoin, 0);
    gather_kernel<<<(N * 32 + 255) / 256, 256>>>(N);

    node_mma<<<nblk, NTHREADS, SMEM_MMA_BYTES>>>(x, ub1, ub2, out, N);
}

// round 11
// speedup vs baseline: 1.3136x; 1.0268x over previous
#include <cuda_runtime.h>
#include <cuda_bf16.h>
#include <cstdint>

#define D 128
#define NTHREADS 256
#define PA 68           // A-tile pair-word row pitch (64 kp + 4 pad); bank = 4r+t, conflict-free
#define PB 136          // B-tile row pitch over n=128 (+8 pad); bank = 8t+r, conflict-free

#define MAX_N 50000
#define MAX_E 800000

// Scratch (static device globals; no allocations allowed)
__device__ float g_P1[(size_t)MAX_N * D];   // X @ msg_w1[0:128]
__device__ float g_P2[(size_t)MAX_N * D];   // X @ msg_w1[128:256] + msg_b1
__device__ float g_H [(size_t)MAX_N * D];   // per-dst sum of relu(P1[src]+P2'[dst])
__device__ float g_U [(size_t)MAX_N * D];   // X @ upd_w1_top (nodeA output)
__device__ float g_deg[MAX_N];              // in-degree (float)
__device__ float g_Wp[D * D];               // msg_w2 @ upd_w1[128:256]
__device__ float g_bp[D];                   // msg_b2 @ upd_w1[128:256]

// Pre-split weight planes: [sel][plane(hi=0,lo=1)][kp 0..63][n 0..127] packed bf16x2
// sel: 0=mw1_top 1=mw1_bot 2=uw1_top 3=Wp 4=uw2
__device__ uint32_t g_WS[5 * 2 * 64 * 128];

// CSR scratch
__device__ int g_cnt[MAX_N];
__device__ int g_off[MAX_N + 1];
__device__ int g_cur[MAX_N];
__device__ int g_esrc[MAX_E];

// ---------------------------------------------------------------------------
__global__ void zero_cnt_kernel(int N) {
    int i = blockIdx.x * blockDim.x + threadIdx.x;
    if (i < N) g_cnt[i] = 0;
}

// ---------------------------------------------------------------------------
// W' = msg_w2 @ upd_w1_bot  and  b' = msg_b2 @ upd_w1_bot   (tiny, per launch)
__global__ void wprime_kernel(const float* __restrict__ w2,
                              const float* __restrict__ uw1,
                              const float* __restrict__ b2) {
    int idx = blockIdx.x * 256 + threadIdx.x;
    if (blockIdx.x < 64) {
        int k = idx >> 7;
        int c = idx & 127;
        float s = 0.f;
        #pragma unroll 8
        for (int j = 0; j < D; ++j)
            s += __ldg(w2 + k * D + j) * __ldg(uw1 + (size_t)(D + j) * D + c);
        g_Wp[k * D + c] = s;
    } else if (threadIdx.x < D) {
        int c = threadIdx.x;
        float s = 0.f;
        #pragma unroll 8
        for (int j = 0; j < D; ++j)
            s += __ldg(b2 + j) * __ldg(uw1 + (size_t)(D + j) * D + c);
        g_bp[c] = s;
    }
}

// ---------------------------------------------------------------------------
// Split (x,y) [k, k+1 adjacent] into hi/lo packed bf16x2 words.
__device__ __forceinline__ void split2(float x, float y, uint32_t& hi, uint32_t& lo) {
    __nv_bfloat162 hp = __floats2bfloat162_rn(x, y);
    float xh = __low2float(hp);
    float yh = __high2float(hp);
    __nv_bfloat162 lp = __floats2bfloat162_rn(x - xh, y - yh);
    hi = *reinterpret_cast<uint32_t*>(&hp);
    lo = *reinterpret_cast<uint32_t*>(&lp);
}

// Split all five B matrices into g_WS (run after wprime; sel=3 reads g_Wp).
__global__ void split_weights_kernel(const float* __restrict__ mw1,
                                     const float* __restrict__ uw1,
                                     const float* __restrict__ uw2) {
    int sel = blockIdx.y;
    const float* w;
    if      (sel == 0) w = mw1;
    else if (sel == 1) w = mw1 + (size_t)128 * D;
    else if (sel == 2) w = uw1;
    else if (sel == 3) w = g_Wp;
    else               w = uw2;
    int i = blockIdx.x * 256 + threadIdx.x;   // 0..8191
    if (i < 8192) {
        int kp = i >> 7, n = i & 127;
        float xv = __ldg(w + (size_t)(2 * kp) * D + n);
        float yv = __ldg(w + (size_t)(2 * kp + 1) * D + n);
        uint32_t h, l;
        split2(xv, yv, h, l);
        g_WS[(size_t)sel * 16384 + kp * 128 + n]        = h;
        g_WS[(size_t)sel * 16384 + 8192 + kp * 128 + n] = l;
    }
}

// ---------------------------------------------------------------------------
// CSR build: histogram -> scan -> scatter
__global__ void hist_kernel(const int* __restrict__ ei, int E) {
    int i = blockIdx.x * blockDim.x + threadIdx.x;
    if (i < E) {
        int2 e = __ldg((const int2*)ei + i);
        atomicAdd(&g_cnt[e.y], 1);
    }
}

__global__ __launch_bounds__(1024) void scan_kernel(int N, int E) {
    __shared__ int part[1024];
    int t = threadIdx.x;
    int chunk = (N + 1023) >> 10;
    int beg = t * chunk;
    int end = beg + chunk; if (end > N) end = N;
    int s = 0;
    for (int i = beg; i < end; ++i) s += g_cnt[i];
    part[t] = s;
    __syncthreads();
    for (int off = 1; off < 1024; off <<= 1) {
        int v = (t >= off) ? part[t - off] : 0;
        __syncthreads();
        part[t] += v;
        __syncthreads();
    }
    int run = (t == 0) ? 0 : part[t - 1];
    for (int i = beg; i < end; ++i) {
        g_off[i] = run;
        g_cur[i] = run;
        run += g_cnt[i];
    }
    if (t == 0) g_off[N] = E;
}

__global__ void scatter_kernel(const int* __restrict__ ei, int E) {
    int i = blockIdx.x * blockDim.x + threadIdx.x;
    if (i < E) {
        int2 e = __ldg((const int2*)ei + i);
        int pos = atomicAdd(&g_cur[e.y], 1);
        g_esrc[pos] = e.x;
    }
}

// ---------------------------------------------------------------------------
// Gather: one warp per dst node. H[d] = sum_e relu(P1[src_e] + P2'[d]); no atomics.
__global__ __launch_bounds__(256)
void gather_kernel(int N) {
    int d = (int)((blockIdx.x * 256 + threadIdx.x) >> 5);
    int lane = threadIdx.x & 31;
    if (d >= N) return;
    int beg = __ldg(&g_off[d]);
    int end = __ldg(&g_off[d + 1]);
    float4 p2 = __ldg((const float4*)(g_P2 + (size_t)d * D) + lane);
    float4 acc = make_float4(0.f, 0.f, 0.f, 0.f);
    int j = beg;
    for (; j + 1 < end; j += 2) {
        int s0 = __ldg(g_esrc + j);
        int s1 = __ldg(g_esrc + j + 1);
        float4 a = __ldg((const float4*)(g_P1 + (size_t)s0 * D) + lane);
        float4 b = __ldg((const float4*)(g_P1 + (size_t)s1 * D) + lane);
        acc.x += fmaxf(a.x + p2.x, 0.f) + fmaxf(b.x + p2.x, 0.f);
        acc.y += fmaxf(a.y + p2.y, 0.f) + fmaxf(b.y + p2.y, 0.f);
        acc.z += fmaxf(a.z + p2.z, 0.f) + fmaxf(b.z + p2.z, 0.f);
        acc.w += fmaxf(a.w + p2.w, 0.f) + fmaxf(b.w + p2.w, 0.f);
    }
    if (j < end) {
        int s0 = __ldg(g_esrc + j);
        float4 a = __ldg((const float4*)(g_P1 + (size_t)s0 * D) + lane);
        acc.x += fmaxf(a.x + p2.x, 0.f);
        acc.y += fmaxf(a.y + p2.y, 0.f);
        acc.z += fmaxf(a.z + p2.z, 0.f);
        acc.w += fmaxf(a.w + p2.w, 0.f);
    }
    *((float4*)(g_H + (size_t)d * D) + lane) = acc;
    if (lane == 0) g_deg[d] = (float)(end - beg);
}

// ===========================================================================
// bf16x3 tensor-core GEMM: acc += Ah*Bh + Al*Bh + Ah*Bl (Al*Bl dropped, ~2^-16)
// Block tile 128x128, warp grid 2x4 -> warp tile m64 x n32, full-K resident.
// ===========================================================================

__device__ __forceinline__ void mma16816(float c[4],
                                         uint32_t a0, uint32_t a1, uint32_t a2, uint32_t a3,
                                         uint32_t b0, uint32_t b1) {
    asm volatile(
        "mma.sync.aligned.m16n8k16.row.col.f32.bf16.bf16.f32 "
        "{%0,%1,%2,%3}, {%4,%5,%6,%7}, {%8,%9}, {%0,%1,%2,%3};"
        : "+f"(c[0]), "+f"(c[1]), "+f"(c[2]), "+f"(c[3])
        : "r"(a0), "r"(a1), "r"(a2), "r"(a3), "r"(b0), "r"(b1));
}

// Fill A tile (128 rows x 64 kp), pre-split, from global f32 [rows][128].
__device__ __forceinline__ void fill_A(uint32_t* sA0, uint32_t* sA1,
                                       const float* __restrict__ src,
                                       int rowBase, int N, int tid) {
    for (int i = tid; i < 128 * 64; i += NTHREADS) {
        int m = i >> 6, kp = i & 63;
        int gm = rowBase + m;
        float2 v = make_float2(0.f, 0.f);
        if (gm < N) v = *(const float2*)(src + (size_t)gm * D + 2 * kp);
        uint32_t h, l;
        split2(v.x, v.y, h, l);
        sA0[m * PA + kp] = h;
        sA1[m * PA + kp] = l;
    }
}

// Copy pre-split B matrix sel (full 64 kp x 128 n, both planes) into smem.
__device__ __forceinline__ void fill_B(uint32_t* sB0, uint32_t* sB1, int sel, int tid) {
    const uint32_t* src = g_WS + (size_t)sel * 16384;
    for (int i = tid; i < 64 * 32; i += NTHREADS) {
        int kp = i >> 5, n4 = (i & 31) * 4;
        uint4 h = *(const uint4*)(src + kp * 128 + n4);
        uint4 l = *(const uint4*)(src + 8192 + kp * 128 + n4);
        *(uint4*)(sB0 + kp * PB + n4) = h;
        *(uint4*)(sB1 + kp * PB + n4) = l;
    }
}

// Full-K mma pass. Warp tile: rows [64*wm, +64), cols [32*wn, +32).
__device__ __forceinline__ void mma_full(const uint32_t* sA0, const uint32_t* sA1,
                                         const uint32_t* sB0, const uint32_t* sB1,
                                         float acc[4][4][4], int wm, int wn, int r, int t) {
    #pragma unroll
    for (int ks = 0; ks < 8; ++ks) {
        int kpA = ks * 8;
        uint32_t ah[4][4], al[4][4];
        #pragma unroll
        for (int mi = 0; mi < 4; ++mi) {
            int m0 = 64 * wm + 16 * mi + r;
            const uint32_t* p0 = sA0 + m0 * PA + kpA;
            const uint32_t* p1 = sA0 + (m0 + 8) * PA + kpA;
            const uint32_t* q0 = sA1 + m0 * PA + kpA;
            const uint32_t* q1 = sA1 + (m0 + 8) * PA + kpA;
            ah[mi][0] = p0[t]; ah[mi][1] = p1[t]; ah[mi][2] = p0[4 + t]; ah[mi][3] = p1[4 + t];
            al[mi][0] = q0[t]; al[mi][1] = q1[t]; al[mi][2] = q0[4 + t]; al[mi][3] = q1[4 + t];
        }
        #pragma unroll
        for (int ni = 0; ni < 4; ++ni) {
            int n = 32 * wn + 8 * ni + r;
            uint32_t bh0 = sB0[(ks * 8 + t) * PB + n];
            uint32_t bh1 = sB0[(ks * 8 + 4 + t) * PB + n];
            uint32_t bl0 = sB1[(ks * 8 + t) * PB + n];
            uint32_t bl1 = sB1[(ks * 8 + 4 + t) * PB + n];
            #pragma unroll
            for (int mi = 0; mi < 4; ++mi) {
                mma16816(acc[mi][ni], ah[mi][0], ah[mi][1], ah[mi][2], ah[mi][3], bh0, bh1);
                mma16816(acc[mi][ni], al[mi][0], al[mi][1], al[mi][2], al[mi][3], bh0, bh1);
                mma16816(acc[mi][ni], ah[mi][0], ah[mi][1], ah[mi][2], ah[mi][3], bl0, bl1);
            }
        }
    }
}

__device__ __forceinline__ void zero_acc(float acc[4][4][4]) {
    #pragma unroll
    for (int mi = 0; mi < 4; ++mi)
        #pragma unroll
        for (int ni = 0; ni < 4; ++ni)
            #pragma unroll
            for (int q = 0; q < 4; ++q) acc[mi][ni][q] = 0.f;
}

// smem word offsets
#define SA0_OFF 0
#define SA1_OFF (128 * PA)
#define SB0_OFF (2 * 128 * PA)
#define SB1_OFF (2 * 128 * PA + 64 * PB)
#define SMEM_MMA_BYTES ((2 * 128 * PA + 2 * 64 * PB) * 4)   // 139264 B

// ---------------------------------------------------------------------------
// K1: P1 = X @ mw1_top, P2 = X @ mw1_bot + b1
__global__ __launch_bounds__(256)
void precompute_mma(const float* __restrict__ x, const float* __restrict__ b1, int N) {
    extern __shared__ uint32_t smu[];
    uint32_t* sA0 = smu + SA0_OFF;
    uint32_t* sA1 = smu + SA1_OFF;
    uint32_t* sB0 = smu + SB0_OFF;
    uint32_t* sB1 = smu + SB1_OFF;
    const int tid = threadIdx.x;
    const int wid = tid >> 5, lane = tid & 31;
    const int wm = wid >> 2, wn = wid & 3, r = lane >> 2, t = lane & 3;
    const int rowBase = blockIdx.x * 128;

    fill_A(sA0, sA1, x, rowBase, N, tid);
    fill_B(sB0, sB1, 0, tid);
    __syncthreads();

    float acc[4][4][4];
    zero_acc(acc);
    mma_full(sA0, sA1, sB0, sB1, acc, wm, wn, r, t);
    __syncthreads();                       // release B before refill

    #pragma unroll
    for (int mi = 0; mi < 4; ++mi) {
        int m0 = rowBase + 64 * wm + 16 * mi + r;
        int m1 = m0 + 8;
        #pragma unroll
        for (int ni = 0; ni < 4; ++ni) {
            int col = 32 * wn + 8 * ni + 2 * t;
            if (m0 < N) *(float2*)(g_P1 + (size_t)m0 * D + col) = make_float2(acc[mi][ni][0], acc[mi][ni][1]);
            if (m1 < N) *(float2*)(g_P1 + (size_t)m1 * D + col) = make_float2(acc[mi][ni][2], acc[mi][ni][3]);
        }
    }

    fill_B(sB0, sB1, 1, tid);
    __syncthreads();
    zero_acc(acc);
    mma_full(sA0, sA1, sB0, sB1, acc, wm, wn, r, t);

    #pragma unroll
    for (int mi = 0; mi < 4; ++mi) {
        int m0 = rowBase + 64 * wm + 16 * mi + r;
        int m1 = m0 + 8;
        #pragma unroll
        for (int ni = 0; ni < 4; ++ni) {
            int col = 32 * wn + 8 * ni + 2 * t;
            float b0 = __ldg(b1 + col), bx = __ldg(b1 + col + 1);
            if (m0 < N) *(float2*)(g_P2 + (size_t)m0 * D + col) = make_float2(acc[mi][ni][0] + b0, acc[mi][ni][1] + bx);
            if (m1 < N) *(float2*)(g_P2 + (size_t)m1 * D + col) = make_float2(acc[mi][ni][2] + b0, acc[mi][ni][3] + bx);
        }
    }
}

// ---------------------------------------------------------------------------
// nodeA: U = X @ uw1_top  (independent of gather; overlaps it on stream 2)
__global__ __launch_bounds__(256)
void nodeA_mma(const float* __restrict__ x, int N) {
    extern __shared__ uint32_t smu[];
    uint32_t* sA0 = smu + SA0_OFF;
    uint32_t* sA1 = smu + SA1_OFF;
    uint32_t* sB0 = smu + SB0_OFF;
    uint32_t* sB1 = smu + SB1_OFF;
    const int tid = threadIdx.x;
    const int wid = tid >> 5, lane = tid & 31;
    const int wm = wid >> 2, wn = wid & 3, r = lane >> 2, t = lane & 3;
    const int rowBase = blockIdx.x * 128;

    fill_A(sA0, sA1, x, rowBase, N, tid);
    fill_B(sB0, sB1, 2, tid);
    __syncthreads();

    float acc[4][4][4];
    zero_acc(acc);
    mma_full(sA0, sA1, sB0, sB1, acc, wm, wn, r, t);

    #pragma unroll
    for (int mi = 0; mi < 4; ++mi) {
        int m0 = rowBase + 64 * wm + 16 * mi + r;
        int m1 = m0 + 8;
        #pragma unroll
        for (int ni = 0; ni < 4; ++ni) {
            int col = 32 * wn + 8 * ni + 2 * t;
            if (m0 < N) *(float2*)(g_U + (size_t)m0 * D + col) = make_float2(acc[mi][ni][0], acc[mi][ni][1]);
            if (m1 < N) *(float2*)(g_U + (size_t)m1 * D + col) = make_float2(acc[mi][ni][2], acc[mi][ni][3]);
        }
    }
}

// ---------------------------------------------------------------------------
// nodeB: out = relu(U + H@W' + deg*b' + ub1) @ uw2 + ub2
__global__ __launch_bounds__(256)
void nodeB_mma(const float* __restrict__ ub1, const float* __restrict__ ub2,
               float* __restrict__ out, int N) {
    extern __shared__ uint32_t smu[];
    uint32_t* sA0 = smu + SA0_OFF;
    uint32_t* sA1 = smu + SA1_OFF;
    uint32_t* sB0 = smu + SB0_OFF;
    uint32_t* sB1 = smu + SB1_OFF;
    const int tid = threadIdx.x;
    const int wid = tid >> 5, lane = tid & 31;
    const int wm = wid >> 2, wn = wid & 3, r = lane >> 2, t = lane & 3;
    const int rowBase = blockIdx.x * 128;

    float acc[4][4][4];
    zero_acc(acc);

    // ---- H @ Wp ----
    fill_A(sA0, sA1, g_H, rowBase, N, tid);
    fill_B(sB0, sB1, 3, tid);
    __syncthreads();
    mma_full(sA0, sA1, sB0, sB1, acc, wm, wn, r, t);
    __syncthreads();                       // all reads of sA done before epilogue writes

    // ---- epilogue 1: + U + deg*b' + ub1, relu ; re-split hidden into sA planes ----
    #pragma unroll
    for (int mi = 0; mi < 4; ++mi) {
        int m0 = rowBase + 64 * wm + 16 * mi + r;
        int m1 = m0 + 8;
        float dg0 = (m0 < N) ? __ldg(g_deg + m0) : 0.f;
        float dg1 = (m1 < N) ? __ldg(g_deg + m1) : 0.f;
        #pragma unroll
        for (int ni = 0; ni < 4; ++ni) {
            int col = 32 * wn + 8 * ni + 2 * t;
            float2 uv0 = (m0 < N) ? *(const float2*)(g_U + (size_t)m0 * D + col) : make_float2(0.f, 0.f);
            float2 uv1 = (m1 < N) ? *(const float2*)(g_U + (size_t)m1 * D + col) : make_float2(0.f, 0.f);
            float bp0 = g_bp[col], bp1 = g_bp[col + 1];
            float u0 = __ldg(ub1 + col), u1 = __ldg(ub1 + col + 1);
            float v00 = fmaxf(acc[mi][ni][0] + uv0.x + dg0 * bp0 + u0, 0.f);
            float v01 = fmaxf(acc[mi][ni][1] + uv0.y + dg0 * bp1 + u1, 0.f);
            float v10 = fmaxf(acc[mi][ni][2] + uv1.x + dg1 * bp0 + u0, 0.f);
            float v11 = fmaxf(acc[mi][ni][3] + uv1.y + dg1 * bp1 + u1, 0.f);
            int kp = 16 * wn + 4 * ni + t;
            int lm0 = 64 * wm + 16 * mi + r;
            uint32_t h, l;
            split2(v00, v01, h, l);
            sA0[lm0 * PA + kp] = h;
            sA1[lm0 * PA + kp] = l;
            split2(v10, v11, h, l);
            sA0[(lm0 + 8) * PA + kp] = h;
            sA1[(lm0 + 8) * PA + kp] = l;
        }
    }
    fill_B(sB0, sB1, 4, tid);              // overlaps epilogue; disjoint smem region
    __syncthreads();

    // ---- hidden @ uw2 ----
    zero_acc(acc);
    mma_full(sA0, sA1, sB0, sB1, acc, wm, wn, r, t);

    #pragma unroll
    for (int mi = 0; mi < 4; ++mi) {
        int m0 = rowBase + 64 * wm + 16 * mi + r;
        int m1 = m0 + 8;
        #pragma unroll
        for (int ni = 0; ni < 4; ++ni) {
            int col = 32 * wn + 8 * ni + 2 * t;
            float b0 = __ldg(ub2 + col), bx = __ldg(ub2 + col + 1);
            if (m0 < N) *(float2*)(out + (size_t)m0 * D + col) = make_float2(acc[mi][ni][0] + b0, acc[mi][ni][1] + bx);
            if (m1 < N) *(float2*)(out + (size_t)m1 * D + col) = make_float2(acc[mi][ni][2] + b0, acc[mi][ni][3] + bx);
        }
    }
}

// ---------------------------------------------------------------------------
extern "C" void kernel_launch(void* const* d_in, const int* in_sizes, int n_in,
                              void* d_out, int out_size) {
    const float* x   = (const float*)d_in[0];
    const int*   ei  = (const int*)d_in[1];     // int64 downcast to int32 by harness
    const float* mw1 = (const float*)d_in[2];
    const float* mb1 = (const float*)d_in[3];
    const float* mw2 = (const float*)d_in[4];
    const float* mb2 = (const float*)d_in[5];
    const float* uw1 = (const float*)d_in[6];
    const float* ub1 = (const float*)d_in[7];
    const float* uw2 = (const float*)d_in[8];
    const float* ub2 = (const float*)d_in[9];
    float* out = (float*)d_out;

    int N = in_sizes[0] / D;
    int E = in_sizes[1] / 2;

    cudaFuncSetAttribute(precompute_mma, cudaFuncAttributeMaxDynamicSharedMemorySize, SMEM_MMA_BYTES);
    cudaFuncSetAttribute(nodeA_mma,      cudaFuncAttributeMaxDynamicSharedMemorySize, SMEM_MMA_BYTES);
    cudaFuncSetAttribute(nodeB_mma,      cudaFuncAttributeMaxDynamicSharedMemorySize, SMEM_MMA_BYTES);

    // One-time side-stream + events (created on the uncaptured correctness
    // call; reused as-is during graph capture). No device memory allocated.
    static cudaStream_t s2 = nullptr;
    static cudaEvent_t evFork = nullptr, evJoin = nullptr, evP = nullptr, evA = nullptr;
    if (s2 == nullptr) {
        cudaStreamCreateWithFlags(&s2, cudaStreamNonBlocking);
        cudaEventCreateWithFlags(&evFork, cudaEventDisableTiming);
        cudaEventCreateWithFlags(&evJoin, cudaEventDisableTiming);
        cudaEventCreateWithFlags(&evP,    cudaEventDisableTiming);
        cudaEventCreateWithFlags(&evA,    cudaEventDisableTiming);
    }

    int eblk = (E + 255) / 256;
    int nblk = (N + 127) / 128;

    // main stream: counters zeroed first (hist depends on them)
    zero_cnt_kernel<<<(N + 255) / 256, 256>>>(N);

    // fork: CSR build (depends only on ei) runs concurrently with weight prep + K1
    cudaEventRecord(evFork, 0);
    cudaStreamWaitEvent(s2, evFork, 0);
    hist_kernel<<<eblk, 256, 0, s2>>>(ei, E);
    scan_kernel<<<1, 1024, 0, s2>>>(N, E);
    scatter_kernel<<<eblk, 256, 0, s2>>>(ei, E);
    cudaEventRecord(evJoin, s2);

    // main stream: weight prep + precompute GEMMs (tensor-bound, hides CSR)
    wprime_kernel<<<65, 256>>>(mw2, uw1, mb2);
    split_weights_kernel<<<dim3(32, 5), 256>>>(mw1, uw1, uw2);
    precompute_mma<<<nblk, NTHREADS, SMEM_MMA_BYTES>>>(x, mb1, N);
    cudaEventRecord(evP, 0);

    // s2: nodeA (U = X @ uw1_top) gated on precompute so it overlaps GATHER,
    // not precompute (both tensor-bound; gather is memory-bound -> complementary)
    cudaStreamWaitEvent(s2, evP, 0);
    nodeA_mma<<<nblk, NTHREADS, SMEM_MMA_BYTES, s2>>>(x, N);
    cudaEventRecord(evA, s2);

    // main: gather (needs P1/P2 + CSR) runs concurrently with nodeA
    cudaStreamWaitEvent(0, evJoin, 0);
    gather_kernel<<<(N * 32 + 255) / 256, 256>>>(N);

    // join nodeA, then final fused GEMM
    cudaStreamWaitEvent(0, evA, 0);
    nodeB_mma<<<nblk, NTHREADS, SMEM_MMA_BYTES>>>(ub1, ub2, out, N);
}